// round 2
// baseline (speedup 1.0000x reference)
#include <cuda_runtime.h>

#define TW 64
#define TH 32
#define NT 256

#define GW (TW + 12)   // 76  gray cols, base ox-6
#define GH (TH + 12)   // 44  gray rows, base oy-6
#define HBW (TW + 8)   // 72  hblur cols, base ox-4 (rows base oy-6)
#define HBH (TH + 12)  // 44
#define BW (TW + 8)    // 72  blur cols, base ox-4
#define BH (TH + 8)    // 40  blur rows, base oy-4
#define MW (TW + 6)    // 70  mag cols, base ox-3
#define MH (TH + 6)    // 38  mag rows, base oy-3
#define NW (TW + 4)    // 68  nms cols, base ox-2
#define NH (TH + 4)    // 36  nms rows, base oy-2
#define RW TW          // 64  rowmax cols, base ox
#define RH (TH + 4)    // 36  rowmax rows, base oy-2

__global__ __launch_bounds__(NT) void canny_edge_kernel(
    const float* __restrict__ x, float* __restrict__ out)
{
    // A: gray -> blur -> nms   (max 3344 floats)
    // B: hblur -> mag -> rowmax (max 3168 floats)
    __shared__ float A[GH * GW];
    __shared__ float B[HBH * HBW];
    __shared__ unsigned char C[MH * MW];  // gradient axis (0..3)

    const int tid = threadIdx.x;
    const int ox = blockIdx.x * TW;
    const int oy = blockIdx.y * TH;
    const int n  = blockIdx.z;

    // float32-accurate Gaussian(5, sigma=1) taps
    const float gk0 = 0.054488685f;
    const float gk1 = 0.244201342f;
    const float gk2 = 0.402619947f;
    const float gk[5] = {gk0, gk1, gk2, gk1, gk0};

    const float* c0 = x + ((size_t)n * 3 + 0) * 512 * 512;
    const float* c1 = x + ((size_t)n * 3 + 1) * 512 * 512;
    const float* c2 = x + ((size_t)n * 3 + 2) * 512 * 512;

    // ---- Stage 1: grayscale (channel order reversed by reference) ----
    for (int i = tid; i < GH * GW; i += NT) {
        int lr = i / GW, lc = i - lr * GW;
        int gy = oy - 6 + lr, gx = ox - 6 + lc;
        float v = 0.f;
        if ((unsigned)gy < 512u && (unsigned)gx < 512u) {
            int idx = gy * 512 + gx;
            v = 0.299f * c2[idx] + 0.587f * c1[idx] + 0.114f * c0[idx];
        }
        A[i] = v;
    }
    __syncthreads();

    // ---- Stage 2: horizontal Gaussian blur (reflect pad, width 2) into B ----
    for (int i = tid; i < HBH * HBW; i += NT) {
        int lr = i / HBW, lc = i - lr * HBW;
        int gx = ox - 4 + lc;
        float s = 0.f;
#pragma unroll
        for (int k = 0; k < 5; k++) {
            int c = gx + k - 2;
            c = (c < 0) ? -c : ((c > 511) ? 1022 - c : c);
            int lcg = c - (ox - 6);
            lcg = min(max(lcg, 0), GW - 1);
            s += gk[k] * A[lr * GW + lcg];
        }
        B[i] = s;
    }
    __syncthreads();

    // ---- Stage 3: vertical Gaussian blur (reflect pad) into A ----
    for (int i = tid; i < BH * BW; i += NT) {
        int lr = i / BW, lc = i - lr * BW;
        int gy = oy - 4 + lr;
        float s = 0.f;
#pragma unroll
        for (int k = 0; k < 5; k++) {
            int r = gy + k - 2;
            r = (r < 0) ? -r : ((r > 511) ? 1022 - r : r);
            int lrh = r - (oy - 6);
            lrh = min(max(lrh, 0), HBH - 1);
            s += gk[k] * B[lrh * HBW + lc];
        }
        A[lr * BW + lc] = s;
    }
    __syncthreads();

    // ---- Stage 4: Sobel (edge/replicate pad) + magnitude into B, axis into C ----
    for (int i = tid; i < MH * MW; i += NT) {
        int lr = i / MW, lc = i - lr * MW;
        int gy = oy - 3 + lr, gx = ox - 3 + lc;
        float m = 0.f;
        int ax = 0;
        if ((unsigned)gy < 512u && (unsigned)gx < 512u) {
            int cym = min(max(gy - 1, 0), 511) - (oy - 4);
            int cy0 = gy - (oy - 4);
            int cyp = min(max(gy + 1, 0), 511) - (oy - 4);
            int cxm = min(max(gx - 1, 0), 511) - (ox - 4);
            int cx0 = gx - (ox - 4);
            int cxp = min(max(gx + 1, 0), 511) - (ox - 4);
            float bmm = A[cym * BW + cxm], bm0 = A[cym * BW + cx0], bmp = A[cym * BW + cxp];
            float b0m = A[cy0 * BW + cxm],                          b0p = A[cy0 * BW + cxp];
            float bpm = A[cyp * BW + cxm], bp0 = A[cyp * BW + cx0], bpp = A[cyp * BW + cxp];
            float sx = 0.125f * (bmp - bmm) + 0.25f * (b0p - b0m) + 0.125f * (bpp - bpm);
            float sy = 0.125f * (bpm - bmm) + 0.25f * (bp0 - bm0) + 0.125f * (bpp - bmp);
            m = sqrtf(sx * sx + sy * sy + 1e-6f);
            // axis = round(atan2(sy,sx)*4/pi) mod 4, via tan(22.5)/tan(67.5) compares.
            // Boundary <=/>= choices reproduce round-half-even exactly.
            float adx = fabsf(sx), ady = fabsf(sy);
            const float t1 = 0.41421356237f;  // tan(22.5 deg)
            const float t2 = 2.41421356237f;  // tan(67.5 deg)
            if (ady <= adx * t1)       ax = 0;
            else if (ady >= adx * t2)  ax = 2;
            else                       ax = ((sx > 0.f) == (sy > 0.f)) ? 1 : 3;
        }
        B[i] = m;
        C[i] = (unsigned char)ax;
    }
    __syncthreads();

    // ---- Stage 5: NMS into A ----
    for (int i = tid; i < NH * NW; i += NT) {
        int lr = i / NW, lc = i - lr * NW;
        int gy = oy - 2 + lr, gx = ox - 2 + lc;
        float v = 0.f;
        if ((unsigned)gy < 512u && (unsigned)gx < 512u) {
            int mi = (lr + 1) * MW + (lc + 1);
            float m = B[mi];
            int ax = C[mi];
            int dy = (ax == 0) ? 0 : 1;
            int dx = (ax == 2) ? 0 : ((ax == 3) ? -1 : 1);
            float n1 = B[(lr + 1 + dy) * MW + (lc + 1 + dx)];
            float n2 = B[(lr + 1 - dy) * MW + (lc + 1 - dx)];
            v = (m > n1 && m > n2) ? m : 0.f;
        }
        A[lr * NW + lc] = v;
    }
    __syncthreads();

    // ---- Stage 6: 5-wide row max into B ----
    for (int i = tid; i < RH * RW; i += NT) {
        int lr = i / RW, lc = i - lr * RW;
        const float* row = &A[lr * NW + lc];
        float v = row[0];
        v = fmaxf(v, row[1]);
        v = fmaxf(v, row[2]);
        v = fmaxf(v, row[3]);
        v = fmaxf(v, row[4]);
        B[i] = v;
    }
    __syncthreads();

    // ---- Stage 7: 5-tall col max, write out ----
    for (int i = tid; i < TH * TW; i += NT) {
        int lr = i / TW, lc = i - lr * TW;
        float v = B[lr * RW + lc];
        v = fmaxf(v, B[(lr + 1) * RW + lc]);
        v = fmaxf(v, B[(lr + 2) * RW + lc]);
        v = fmaxf(v, B[(lr + 3) * RW + lc]);
        v = fmaxf(v, B[(lr + 4) * RW + lc]);
        out[((size_t)n * 512 + (oy + lr)) * 512 + (ox + lc)] = v;
    }
}

extern "C" void kernel_launch(void* const* d_in, const int* in_sizes, int n_in,
                              void* d_out, int out_size)
{
    const float* x = (const float*)d_in[0];
    float* out = (float*)d_out;
    dim3 grid(512 / TW, 512 / TH, 32);
    canny_edge_kernel<<<grid, NT>>>(x, out);
}

// round 3
// speedup vs baseline: 1.2638x; 1.2638x over previous
#include <cuda_runtime.h>

#define TW 64
#define TH 32
#define NT 256
#define S  80   // unified smem row stride (floats)

// logical extents (base offsets relative to output tile origin ox,oy)
#define GW 76   /* gray  cols, base ox-6 */
#define GH 44   /* gray  rows, base oy-6 */
#define HBW 72  /* hblur cols, base ox-4 (rows base oy-6) */
#define HBH 44
#define BW 72   /* blur cols, base ox-4 */
#define BH 40   /* blur rows, base oy-4 */
#define MW 70   /* mag  cols, base ox-3 */
#define MH 38   /* mag  rows, base oy-3 */
#define NW 68   /* nms  cols, base ox-2 */
#define NH 36   /* nms  rows, base oy-2 */
#define RW 68   /* colmax cols, base ox-2 */
#define RH 32   /* colmax rows, base oy   */

__global__ __launch_bounds__(NT) void canny_edge_kernel(
    const float* __restrict__ x, float* __restrict__ out)
{
    __shared__ float A[GH * S];          // gray -> blur -> nms
    __shared__ float B[GH * S];          // hblur -> mag -> colmax
    __shared__ unsigned char C[MH * S];  // gradient axis (0..3)

    const int tid = threadIdx.x;
    const int tx = tid & 63;
    const int ty = tid >> 6;
    const int ox = blockIdx.x * TW;
    const int oy = blockIdx.y * TH;
    const int n  = blockIdx.z;

    const float gk0 = 0.054488685f;
    const float gk1 = 0.244201342f;
    const float gk2 = 0.402619947f;
    const float gk[5] = {gk0, gk1, gk2, gk1, gk0};

    const float* c0 = x + ((size_t)n * 3 + 0) * 512 * 512;
    const float* c1 = x + ((size_t)n * 3 + 1) * 512 * 512;
    const float* c2 = x + ((size_t)n * 3 + 2) * 512 * 512;

    const bool interior = (ox >= 6) && (ox + TW + 6 <= 512) &&
                          (oy >= 6) && (oy + TH + 6 <= 512);

    const float t1 = 0.41421356237f;  // tan(22.5 deg)
    const float t2 = 2.41421356237f;  // tan(67.5 deg)

    if (interior) {
        // ================= fast interior path (no clamps, no divisions) ======
        // ---- Stage 1: grayscale ----
        {
            const int base = (oy - 6) * 512 + (ox - 6);
            for (int lr = ty; lr < GH; lr += 4) {
                int idx = base + lr * 512 + tx;
                A[lr * S + tx] = 0.299f * c2[idx] + 0.587f * c1[idx] + 0.114f * c0[idx];
                if (tx < GW - 64) {
                    int i2 = idx + 64;
                    A[lr * S + tx + 64] = 0.299f * c2[i2] + 0.587f * c1[i2] + 0.114f * c0[i2];
                }
            }
        }
        __syncthreads();

        // ---- Stage 2: horizontal blur -> B  (hblur col lc taps gray cols lc..lc+4) ----
        for (int lr = ty; lr < HBH; lr += 4) {
            const float* a = &A[lr * S];
            B[lr * S + tx] = gk0 * (a[tx] + a[tx + 4]) + gk1 * (a[tx + 1] + a[tx + 3]) + gk2 * a[tx + 2];
            if (tx < HBW - 64) {
                int c = tx + 64;
                B[lr * S + c] = gk0 * (a[c] + a[c + 4]) + gk1 * (a[c + 1] + a[c + 3]) + gk2 * a[c + 2];
            }
        }
        __syncthreads();

        // ---- Stage 3: vertical blur -> A (blur row lr taps hblur rows lr..lr+4), rolling ----
        {
            int r0 = ty * 10;  // 4 chunks x 10 = 40 rows
            #pragma unroll 2
            for (int pass = 0; pass < 2; pass++) {
                int c = (pass == 0) ? tx : tx + 64;
                if (pass == 1 && tx >= BW - 64) break;
                float w0 = B[(r0 + 0) * S + c];
                float w1 = B[(r0 + 1) * S + c];
                float w2 = B[(r0 + 2) * S + c];
                float w3 = B[(r0 + 3) * S + c];
                #pragma unroll
                for (int j = 0; j < 10; j++) {
                    float w4 = B[(r0 + j + 4) * S + c];
                    A[(r0 + j) * S + c] = gk0 * (w0 + w4) + gk1 * (w1 + w3) + gk2 * w2;
                    w0 = w1; w1 = w2; w2 = w3; w3 = w4;
                }
            }
        }
        __syncthreads();

        // ---- Stage 4: Sobel + magnitude -> B, axis -> C (mag row lr taps blur rows lr..lr+2,
        //      mag col lc taps blur cols lc..lc+2), rolling 3-row window ----
        {
            int r0 = ty * 10;
            int cnt = (ty == 3) ? 8 : 10;  // rows 0..37
            #pragma unroll 2
            for (int pass = 0; pass < 2; pass++) {
                int c = (pass == 0) ? tx : tx + 64;
                if (pass == 1 && tx >= MW - 64) break;
                float l0 = A[(r0 + 0) * S + c], m0 = A[(r0 + 0) * S + c + 1], r_0 = A[(r0 + 0) * S + c + 2];
                float l1 = A[(r0 + 1) * S + c], m1 = A[(r0 + 1) * S + c + 1], r_1 = A[(r0 + 1) * S + c + 2];
                for (int j = 0; j < cnt; j++) {
                    float l2 = A[(r0 + j + 2) * S + c];
                    float m2 = A[(r0 + j + 2) * S + c + 1];
                    float r_2 = A[(r0 + j + 2) * S + c + 2];
                    float sx = 0.125f * (r_0 - l0) + 0.25f * (r_1 - l1) + 0.125f * (r_2 - l2);
                    float sy = 0.125f * (l2 - l0) + 0.25f * (m2 - m0) + 0.125f * (r_2 - r_0);
                    float m = sqrtf(sx * sx + sy * sy + 1e-6f);
                    float adx = fabsf(sx), ady = fabsf(sy);
                    int ax;
                    if (ady <= adx * t1)       ax = 0;
                    else if (ady >= adx * t2)  ax = 2;
                    else                       ax = ((sx > 0.f) == (sy > 0.f)) ? 1 : 3;
                    B[(r0 + j) * S + c] = m;
                    C[(r0 + j) * S + c] = (unsigned char)ax;
                    l0 = l1; m0 = m1; r_0 = r_1;
                    l1 = l2; m1 = m2; r_1 = r_2;
                }
            }
        }
        __syncthreads();

        // ---- Stage 5: NMS -> A (nms (lr,lc) = mag (lr+1,lc+1)) ----
        for (int lr = ty; lr < NH; lr += 4) {
            #pragma unroll 2
            for (int pass = 0; pass < 2; pass++) {
                int lc = (pass == 0) ? tx : tx + 64;
                if (pass == 1 && tx >= NW - 64) break;
                int mi = (lr + 1) * S + (lc + 1);
                float m = B[mi];
                int ax = C[mi];
                int off = (ax == 0) ? 1 : ((ax == 1) ? S + 1 : ((ax == 2) ? S : S - 1));
                float n1 = B[mi + off];
                float n2 = B[mi - off];
                A[lr * S + lc] = (m > n1 && m > n2) ? m : 0.f;
            }
        }
        __syncthreads();

        // ---- Stage 6: vertical 5-max -> B (out row lr taps nms rows lr..lr+4), rolling ----
        {
            int r0 = ty * 8;  // 4 chunks x 8 = 32 rows
            #pragma unroll 2
            for (int pass = 0; pass < 2; pass++) {
                int c = (pass == 0) ? tx : tx + 64;
                if (pass == 1 && tx >= RW - 64) break;
                float w0 = A[(r0 + 0) * S + c];
                float w1 = A[(r0 + 1) * S + c];
                float w2 = A[(r0 + 2) * S + c];
                float w3 = A[(r0 + 3) * S + c];
                #pragma unroll
                for (int j = 0; j < 8; j++) {
                    float w4 = A[(r0 + j + 4) * S + c];
                    B[(r0 + j) * S + c] = fmaxf(fmaxf(fmaxf(w0, w1), fmaxf(w2, w3)), w4);
                    w0 = w1; w1 = w2; w2 = w3; w3 = w4;
                }
            }
        }
        __syncthreads();

        // ---- Stage 7: horizontal 5-max, write out ----
        for (int lr = ty; lr < TH; lr += 4) {
            const float* row = &B[lr * S + tx];
            float v = fmaxf(fmaxf(fmaxf(row[0], row[1]), fmaxf(row[2], row[3])), row[4]);
            out[((size_t)n * 512 + (oy + lr)) * 512 + (ox + tx)] = v;
        }
    } else {
        // ================= boundary path (reflect/edge handling) =============
        for (int i = tid; i < GH * GW; i += NT) {
            int lr = i / GW, lc = i - lr * GW;
            int gy = oy - 6 + lr, gx = ox - 6 + lc;
            float v = 0.f;
            if ((unsigned)gy < 512u && (unsigned)gx < 512u) {
                int idx = gy * 512 + gx;
                v = 0.299f * c2[idx] + 0.587f * c1[idx] + 0.114f * c0[idx];
            }
            A[lr * S + lc] = v;
        }
        __syncthreads();

        for (int i = tid; i < HBH * HBW; i += NT) {
            int lr = i / HBW, lc = i - lr * HBW;
            int gx = ox - 4 + lc;
            float s = 0.f;
            #pragma unroll
            for (int k = 0; k < 5; k++) {
                int c = gx + k - 2;
                c = (c < 0) ? -c : ((c > 511) ? 1022 - c : c);
                int lcg = c - (ox - 6);
                lcg = min(max(lcg, 0), GW - 1);
                s += gk[k] * A[lr * S + lcg];
            }
            B[lr * S + lc] = s;
        }
        __syncthreads();

        for (int i = tid; i < BH * BW; i += NT) {
            int lr = i / BW, lc = i - lr * BW;
            int gy = oy - 4 + lr;
            float s = 0.f;
            #pragma unroll
            for (int k = 0; k < 5; k++) {
                int r = gy + k - 2;
                r = (r < 0) ? -r : ((r > 511) ? 1022 - r : r);
                int lrh = r - (oy - 6);
                lrh = min(max(lrh, 0), HBH - 1);
                s += gk[k] * B[lrh * S + lc];
            }
            A[lr * S + lc] = s;
        }
        __syncthreads();

        for (int i = tid; i < MH * MW; i += NT) {
            int lr = i / MW, lc = i - lr * MW;
            int gy = oy - 3 + lr, gx = ox - 3 + lc;
            float m = 0.f;
            int ax = 0;
            if ((unsigned)gy < 512u && (unsigned)gx < 512u) {
                int cym = min(max(gy - 1, 0), 511) - (oy - 4);
                int cy0 = gy - (oy - 4);
                int cyp = min(max(gy + 1, 0), 511) - (oy - 4);
                int cxm = min(max(gx - 1, 0), 511) - (ox - 4);
                int cx0 = gx - (ox - 4);
                int cxp = min(max(gx + 1, 0), 511) - (ox - 4);
                float bmm = A[cym * S + cxm], bm0 = A[cym * S + cx0], bmp = A[cym * S + cxp];
                float b0m = A[cy0 * S + cxm],                         b0p = A[cy0 * S + cxp];
                float bpm = A[cyp * S + cxm], bp0 = A[cyp * S + cx0], bpp = A[cyp * S + cxp];
                float sx = 0.125f * (bmp - bmm) + 0.25f * (b0p - b0m) + 0.125f * (bpp - bpm);
                float sy = 0.125f * (bpm - bmm) + 0.25f * (bp0 - bm0) + 0.125f * (bpp - bmp);
                m = sqrtf(sx * sx + sy * sy + 1e-6f);
                float adx = fabsf(sx), ady = fabsf(sy);
                if (ady <= adx * t1)       ax = 0;
                else if (ady >= adx * t2)  ax = 2;
                else                       ax = ((sx > 0.f) == (sy > 0.f)) ? 1 : 3;
            }
            B[lr * S + lc] = m;
            C[lr * S + lc] = (unsigned char)ax;
        }
        __syncthreads();

        for (int i = tid; i < NH * NW; i += NT) {
            int lr = i / NW, lc = i - lr * NW;
            int gy = oy - 2 + lr, gx = ox - 2 + lc;
            float v = 0.f;
            if ((unsigned)gy < 512u && (unsigned)gx < 512u) {
                int mi = (lr + 1) * S + (lc + 1);
                float m = B[mi];
                int ax = C[mi];
                int dy = (ax == 0) ? 0 : 1;
                int dx = (ax == 2) ? 0 : ((ax == 3) ? -1 : 1);
                float n1 = B[mi + dy * S + dx];
                float n2 = B[mi - dy * S - dx];
                v = (m > n1 && m > n2) ? m : 0.f;
            }
            A[lr * S + lc] = v;
        }
        __syncthreads();

        // vertical 5-max -> B  (out rows base oy, cols base ox-2)
        for (int i = tid; i < RH * RW; i += NT) {
            int lr = i / RW, lc = i - lr * RW;
            float v = A[(lr + 0) * S + lc];
            v = fmaxf(v, A[(lr + 1) * S + lc]);
            v = fmaxf(v, A[(lr + 2) * S + lc]);
            v = fmaxf(v, A[(lr + 3) * S + lc]);
            v = fmaxf(v, A[(lr + 4) * S + lc]);
            B[lr * S + lc] = v;
        }
        __syncthreads();

        for (int i = tid; i < TH * TW; i += NT) {
            int lr = i >> 6, lc = i & 63;
            const float* row = &B[lr * S + lc];
            float v = fmaxf(fmaxf(fmaxf(row[0], row[1]), fmaxf(row[2], row[3])), row[4]);
            out[((size_t)n * 512 + (oy + lr)) * 512 + (ox + lc)] = v;
        }
    }
}

extern "C" void kernel_launch(void* const* d_in, const int* in_sizes, int n_in,
                              void* d_out, int out_size)
{
    const float* x = (const float*)d_in[0];
    float* out = (float*)d_out;
    dim3 grid(512 / TW, 512 / TH, 32);
    canny_edge_kernel<<<grid, NT>>>(x, out);
}